// round 11
// baseline (speedup 1.0000x reference)
#include <cuda_runtime.h>
#include <cuda_fp16.h>
#include <cstdint>
#include <math.h>

// Problem constants
#define B_    2
#define L_    2048
#define E_    1024
#define H_    16
#define HD_   64
#define KD_   1024
#define NQKV_ 3072
#define ML_   (B_*L_)   // 4096

// ---------------- GEMM tiling (fp16 single product) ----------------
#define BM 128
#define BN 128
#define BK 64
#define ROWB 144
#define B_OFF   (128 * ROWB)
#define STAGEB  (256 * ROWB)        // 36864
#define GEMM_SMEM (2 * STAGEB)      // 73728

// ---------------- attention tiling ----------------
#define AROWB 144
#define QROWS 128
#define KROWS 192
#define S_Q  0
#define S_K  (S_Q + QROWS*AROWB)
#define S_V  (S_K + KROWS*AROWB)
#define S_OK (S_V + KROWS*AROWB)
#define ATTN_SMEM (S_OK + KROWS*4)  // 74496

#define MEGA_SMEM (ATTN_SMEM > GEMM_SMEM ? ATTN_SMEM : GEMM_SMEM)
#define MEGA_CTAS 296

// Ticket layout: converts (wq 48 | x 64 | wo 16) -> gemm1 -> attn -> gemm0
#define T_CVT  128
#define T_G1   768                  // 32 x 24
#define T_ATT  512                  // 16 qb x 2 b x 16 h
#define T_G0   256                  // 32 x 8
#define T_TOT  (T_CVT + T_G1 + T_ATT + T_G0)

// g_sync layout
#define SY_TICK 0
#define SY_G1   1                   // 768
#define SY_FA   769                 // 32
#define SY_FWQ  801                 // 48
#define SY_FX   849                 // 64
#define SY_FWO  913                 // 16
#define SY_DONE 929
#define SY_N    930

// ---------------- scratch ----------------
__device__ __half g_qkv16[(size_t)ML_ * NQKV_];
__device__ __half g_att16[(size_t)ML_ * E_];
__device__ __half g_x16[(size_t)ML_ * KD_];
__device__ __half g_wq16[(size_t)NQKV_ * KD_];
__device__ __half g_wo16[(size_t)E_ * E_];
__device__ unsigned g_sync[SY_N];   // zero-initialized; self-cleaned per launch

// ---------------- helpers ----------------
__device__ __forceinline__ uint32_t smem_u32(const void* p) {
    uint32_t a;
    asm("{ .reg .u64 t; cvta.to.shared.u64 t, %1; cvt.u32.u64 %0, t; }" : "=r"(a) : "l"(p));
    return a;
}
#define CP16(dst, src) \
    asm volatile("cp.async.cg.shared.global [%0], [%1], 16;" :: "r"(dst), "l"(src))
#define CP_COMMIT() asm volatile("cp.async.commit_group;" ::: "memory")
#define CP_WAIT(n)  asm volatile("cp.async.wait_group %0;" :: "n"(n) : "memory")

#define LDSM_X4(r0, r1, r2, r3, a) \
    asm volatile("ldmatrix.sync.aligned.m8n8.x4.shared.b16 {%0,%1,%2,%3}, [%4];" \
                 : "=r"(r0), "=r"(r1), "=r"(r2), "=r"(r3) : "r"(a))
#define LDSM_X4_T(r0, r1, r2, r3, a) \
    asm volatile("ldmatrix.sync.aligned.m8n8.x4.trans.shared.b16 {%0,%1,%2,%3}, [%4];" \
                 : "=r"(r0), "=r"(r1), "=r"(r2), "=r"(r3) : "r"(a))

__device__ __forceinline__ void mma_f16(float c[4], const uint32_t a[4],
                                        uint32_t b0, uint32_t b1) {
    asm volatile(
        "mma.sync.aligned.m16n8k16.row.col.f32.f16.f16.f32 "
        "{%0,%1,%2,%3}, {%4,%5,%6,%7}, {%8,%9}, {%0,%1,%2,%3};"
        : "+f"(c[0]), "+f"(c[1]), "+f"(c[2]), "+f"(c[3])
        : "r"(a[0]), "r"(a[1]), "r"(a[2]), "r"(a[3]), "r"(b0), "r"(b1));
}

__device__ __forceinline__ uint32_t pk_h2(float x, float y) {
    __half2 t = __floats2half2_rn(x, y);
    return *(uint32_t*)&t;
}

__device__ __forceinline__ void spin_flag(volatile unsigned* f) {
    while (*f == 0u) __nanosleep(64);
}

// ---------------------------------------------------------------------------
// One GEMM tile: C[bm:bm+128, bn:bn+128] = A*B^T + bias
// ---------------------------------------------------------------------------
template<bool F16OUT>
__device__ __forceinline__ void gemm_tile(
    char* smem, uint32_t sbase,
    const __half* __restrict__ A, const __half* __restrict__ Bm,
    const float* __restrict__ bias, float* __restrict__ Cf,
    uint32_t* __restrict__ Ch, int bm, int bn, int K, int N)
{
    const int tid  = threadIdx.x;
    const int lane = tid & 31;
    const int wid  = tid >> 5;
    const int warp_m = wid >> 1;
    const int warp_n = wid & 1;
    const int NT = K / BK;

    const int tr = tid >> 3;
    const int lc = tid & 7;
    const __half* Abase = A + (size_t)bm * K;
    const __half* Bbase = Bm + (size_t)bn * K;
    size_t offA[4];
    uint32_t dstA[4];
#pragma unroll
    for (int i = 0; i < 4; ++i) {
        int ra = i * 32 + tr;
        offA[i] = (size_t)ra * K + lc * 8;
        dstA[i] = (uint32_t)(ra * ROWB + lc * 16);
    }

    const uint32_t aOff = (uint32_t)((warp_m * 32 + (lane & 15)) * ROWB + (lane >> 4) * 16);
    const uint32_t bOff = (uint32_t)(B_OFF +
        (warp_n * 64 + ((lane >> 4) << 3) + (lane & 7)) * ROWB + ((lane >> 3) & 1) * 16);

    float acc[2][8][4];
#pragma unroll
    for (int mt = 0; mt < 2; ++mt)
#pragma unroll
        for (int nt = 0; nt < 8; ++nt)
#pragma unroll
            for (int j = 0; j < 4; ++j) acc[mt][nt][j] = 0.0f;

    {
        uint32_t sb = sbase;
#pragma unroll
        for (int i = 0; i < 4; ++i) {
            CP16(sb + dstA[i], Abase + offA[i]);
            CP16(sb + dstA[i] + B_OFF, Bbase + offA[i]);
        }
        CP_COMMIT();
    }

    for (int kt = 0; kt < NT; ++kt) {
        CP_WAIT(0);
        __syncthreads();
        if (kt + 1 < NT) {
            uint32_t sb = sbase + ((kt + 1) & 1) * STAGEB;
            int koff = (kt + 1) * BK;
#pragma unroll
            for (int i = 0; i < 4; ++i) {
                CP16(sb + dstA[i], Abase + offA[i] + koff);
                CP16(sb + dstA[i] + B_OFF, Bbase + offA[i] + koff);
            }
            CP_COMMIT();
        }

        const uint32_t st = sbase + (kt & 1) * STAGEB;
#pragma unroll
        for (int s = 0; s < 4; ++s) {
            uint32_t af[2][4], bf[8][2];
#pragma unroll
            for (int mt = 0; mt < 2; ++mt) {
                uint32_t a = st + aOff + mt * 16 * ROWB + s * 32;
                LDSM_X4(af[mt][0], af[mt][1], af[mt][2], af[mt][3], a);
            }
#pragma unroll
            for (int p = 0; p < 4; ++p) {
                uint32_t a = st + bOff + p * 16 * ROWB + s * 32;
                LDSM_X4(bf[2*p][0], bf[2*p][1], bf[2*p+1][0], bf[2*p+1][1], a);
            }
#pragma unroll
            for (int mt = 0; mt < 2; ++mt)
#pragma unroll
                for (int nt = 0; nt < 8; ++nt)
                    mma_f16(acc[mt][nt], af[mt], bf[nt][0], bf[nt][1]);
        }
        __syncthreads();
    }

    const int r0 = bm + warp_m * 32 + (lane >> 2);
    const int c0 = bn + warp_n * 64 + (lane & 3) * 2;
#pragma unroll
    for (int mt = 0; mt < 2; ++mt) {
#pragma unroll
        for (int nt = 0; nt < 8; ++nt) {
            int col = c0 + nt * 8;
            float bx = bias[col], by = bias[col + 1];
            float vx0 = acc[mt][nt][0] + bx, vy0 = acc[mt][nt][1] + by;
            float vx1 = acc[mt][nt][2] + bx, vy1 = acc[mt][nt][3] + by;
            int ra = r0 + mt * 16, rb = ra + 8;
            if (F16OUT) {
                Ch[(size_t)ra * (N >> 1) + (col >> 1)] = pk_h2(vx0, vy0);
                Ch[(size_t)rb * (N >> 1) + (col >> 1)] = pk_h2(vx1, vy1);
            } else {
                *(float2*)(Cf + (size_t)ra * N + col) = make_float2(vx0, vy0);
                *(float2*)(Cf + (size_t)rb * N + col) = make_float2(vx1, vy1);
            }
        }
    }
}

// ---------------------------------------------------------------------------
// One band-skipping attention tile (b, h, q0..q0+127), 256 threads.
// ---------------------------------------------------------------------------
__device__ __forceinline__ void attn_tile(
    char* smem, uint32_t sb,
    const __half* __restrict__ qkv, const int* __restrict__ pmask,
    uint32_t* __restrict__ Oh, int b, int h, int q0)
{
    const int tid = threadIdx.x, lane = tid & 31, w = tid >> 5;

    for (int i = tid; i < QROWS * 8; i += 256) {
        int r = i >> 3, c = i & 7;
        size_t g = (size_t)(b * L_ + q0 + r) * NQKV_ + h * 192 + c * 8;
        *(uint4*)(smem + S_Q + r * AROWB + c * 16) = *(const uint4*)(qkv + g);
    }
    for (int i = tid; i < KROWS * 8; i += 256) {
        int r = i >> 3, c = i & 7;
        int pos = q0 - 32 + r;
        uint4 kv = make_uint4(0, 0, 0, 0), vv = make_uint4(0, 0, 0, 0);
        if (pos >= 0 && pos < L_) {
            size_t g = (size_t)(b * L_ + pos) * NQKV_ + h * 192 + c * 8;
            kv = *(const uint4*)(qkv + g + 64);
            vv = *(const uint4*)(qkv + g + 128);
        }
        *(uint4*)(smem + S_K + r * AROWB + c * 16) = kv;
        *(uint4*)(smem + S_V + r * AROWB + c * 16) = vv;
    }
    if (tid < KROWS) {
        int pos = q0 - 32 + tid;
        int ok = (pos >= 0 && pos < L_) ? (pmask[b * L_ + pos] != 0) : 0;
        ((int*)(smem + S_OK))[tid] = ok;
    }
    __syncthreads();
    const int* okk = (const int*)(smem + S_OK);

    float S[10][4];
#pragma unroll
    for (int i = 0; i < 10; ++i)
#pragma unroll
        for (int j = 0; j < 4; ++j) S[i][j] = 0.0f;

    uint32_t qf[4][4];
    {
        uint32_t aoff = (uint32_t)((w * 16 + (lane & 15)) * AROWB + (lane >> 4) * 16);
#pragma unroll
        for (int ks = 0; ks < 4; ++ks)
            LDSM_X4(qf[ks][0], qf[ks][1], qf[ks][2], qf[ks][3], sb + S_Q + aoff + ks * 32);
    }
    {
        uint32_t boff = (uint32_t)(((((lane >> 4) << 3) + (lane & 7)) * AROWB) + ((lane >> 3) & 1) * 16);
#pragma unroll
        for (int kbl = 0; kbl < 5; ++kbl) {
            uint32_t base = boff + (w + kbl) * 16 * AROWB;
#pragma unroll
            for (int ks = 0; ks < 4; ++ks) {
                uint32_t b0, b1, b2, b3;
                LDSM_X4(b0, b1, b2, b3, sb + S_K + base + ks * 32);
                mma_f16(S[2 * kbl],     qf[ks], b0, b1);
                mma_f16(S[2 * kbl + 1], qf[ks], b2, b3);
            }
        }
    }

    const int qlo = w * 16 + (lane >> 2);
    const float scale = 0.125f;
    const float NEGS = -12500.0f;
    float mlo = -3.0e38f, mhi = -3.0e38f;
#pragma unroll
    for (int nbl = 0; nbl < 10; ++nbl) {
        int kbl = nbl >> 1, grp = nbl & 1;
#pragma unroll
        for (int p = 0; p < 2; ++p) {
            int j = (w + kbl) * 16 + grp * 8 + (lane & 3) * 2 + p;
            float s0 = S[nbl][p];
            int d0 = j - qlo;
            s0 = (d0 >= 0 && d0 <= 64) ? (okk[j] ? s0 * scale : NEGS) : -3.0e38f;
            S[nbl][p] = s0;
            mlo = fmaxf(mlo, s0);
            float s1 = S[nbl][2 + p];
            int d1 = j - (qlo + 8);
            s1 = (d1 >= 0 && d1 <= 64) ? (okk[j] ? s1 * scale : NEGS) : -3.0e38f;
            S[nbl][2 + p] = s1;
            mhi = fmaxf(mhi, s1);
        }
    }
#pragma unroll
    for (int o = 1; o <= 2; o <<= 1) {
        mlo = fmaxf(mlo, __shfl_xor_sync(0xffffffffu, mlo, o));
        mhi = fmaxf(mhi, __shfl_xor_sync(0xffffffffu, mhi, o));
    }
    float slo = 0.f, shi = 0.f;
#pragma unroll
    for (int nbl = 0; nbl < 10; ++nbl) {
#pragma unroll
        for (int p = 0; p < 2; ++p) {
            float e0 = __expf(S[nbl][p] - mlo);     S[nbl][p] = e0;     slo += e0;
            float e1 = __expf(S[nbl][2 + p] - mhi); S[nbl][2 + p] = e1; shi += e1;
        }
    }
#pragma unroll
    for (int o = 1; o <= 2; o <<= 1) {
        slo += __shfl_xor_sync(0xffffffffu, slo, o);
        shi += __shfl_xor_sync(0xffffffffu, shi, o);
    }
    const float invlo = 1.0f / slo;
    const float invhi = 1.0f / shi;

    uint32_t pf[5][4];
#pragma unroll
    for (int kbl = 0; kbl < 5; ++kbl) {
        pf[kbl][0] = pk_h2(S[2 * kbl][0] * invlo,     S[2 * kbl][1] * invlo);
        pf[kbl][1] = pk_h2(S[2 * kbl][2] * invhi,     S[2 * kbl][3] * invhi);
        pf[kbl][2] = pk_h2(S[2 * kbl + 1][0] * invlo, S[2 * kbl + 1][1] * invlo);
        pf[kbl][3] = pk_h2(S[2 * kbl + 1][2] * invhi, S[2 * kbl + 1][3] * invhi);
    }

    float O[8][4];
#pragma unroll
    for (int i = 0; i < 8; ++i)
#pragma unroll
        for (int j = 0; j < 4; ++j) O[i][j] = 0.0f;

    {
        uint32_t voff = (uint32_t)((lane & 15) * AROWB + (lane >> 4) * 16);
#pragma unroll
        for (int kbl = 0; kbl < 5; ++kbl) {
            uint32_t base = voff + (w + kbl) * 16 * AROWB;
#pragma unroll
            for (int db = 0; db < 4; ++db) {
                uint32_t v0, v1, v2, v3;
                LDSM_X4_T(v0, v1, v2, v3, sb + S_V + base + db * 32);
                mma_f16(O[2 * db],     pf[kbl], v0, v1);
                mma_f16(O[2 * db + 1], pf[kbl], v2, v3);
            }
        }
    }

    const size_t rowlo = (size_t)(b * L_ + q0 + qlo);
    const size_t rowhi = rowlo + 8;
#pragma unroll
    for (int nb = 0; nb < 8; ++nb) {
        int col = h * 64 + nb * 8 + (lane & 3) * 2;
        Oh[rowlo * (E_ / 2) + (col >> 1)] = pk_h2(O[nb][0], O[nb][1]);
        Oh[rowhi * (E_ / 2) + (col >> 1)] = pk_h2(O[nb][2], O[nb][3]);
    }
}

// ---------------------------------------------------------------------------
// Fully fused pipeline: converts -> gemm1 -> attn -> gemm0, flag-gated.
// Self-cleans g_sync at the end (last CTA) for graph replay.
// ---------------------------------------------------------------------------
__global__ __launch_bounds__(256, 2) void mega(
    const float* __restrict__ x, const float* __restrict__ W_qkv,
    const float* __restrict__ W_o,
    const float* __restrict__ b_qkv, const float* __restrict__ b_o,
    const int* __restrict__ pmask, float* __restrict__ out)
{
    extern __shared__ char smem[];
    __shared__ unsigned s_t;
    const uint32_t sbase = smem_u32(smem);
    const int tid = threadIdx.x;
    unsigned* tick = &g_sync[SY_TICK];
    unsigned* g1   = &g_sync[SY_G1];
    unsigned* fa   = &g_sync[SY_FA];
    unsigned* fwq  = &g_sync[SY_FWQ];
    unsigned* fx   = &g_sync[SY_FX];
    unsigned* fwo  = &g_sync[SY_FWO];

    for (;;) {
        __syncthreads();
        if (tid == 0) s_t = atomicAdd(tick, 1u);
        __syncthreads();
        const unsigned t = s_t;
        if (t >= (unsigned)T_TOT) break;

        if (t < (unsigned)T_CVT) {
            // convert one 64-row x 1024-col fp32 chunk to fp16
            const float4* src;
            uint2* dst;
            unsigned* flag;
            if (t < 48u) {            // W_qkv chunks (needed by all gemm1)
                src  = (const float4*)W_qkv + (size_t)t * 16384;
                dst  = (uint2*)g_wq16 + (size_t)t * 16384;
                flag = &fwq[t];
            } else if (t < 112u) {    // x chunks
                unsigned c = t - 48u;
                src  = (const float4*)x + (size_t)c * 16384;
                dst  = (uint2*)g_x16 + (size_t)c * 16384;
                flag = &fx[c];
            } else {                  // W_o chunks
                unsigned c = t - 112u;
                src  = (const float4*)W_o + (size_t)c * 16384;
                dst  = (uint2*)g_wo16 + (size_t)c * 16384;
                flag = &fwo[c];
            }
            for (int i = tid; i < 16384; i += 256) {
                float4 v = src[i];
                dst[i] = make_uint2(pk_h2(v.x, v.y), pk_h2(v.z, v.w));
            }
            __threadfence();
            __syncthreads();
            if (tid == 0) atomicExch(flag, 1u);
        } else if (t < (unsigned)(T_CVT + T_G1)) {
            // QKV projection tile; batches interleaved so early rows finish first
            unsigned u = t - T_CVT;
            int i = (int)u / 24, bn_i = (int)u % 24;
            int bm_i = ((i & 1) << 4) + (i >> 1);
            if (tid == 0) {
                spin_flag(&fwq[2 * bn_i]);
                spin_flag(&fwq[2 * bn_i + 1]);
                spin_flag(&fx[2 * bm_i]);
                spin_flag(&fx[2 * bm_i + 1]);
                __threadfence();
            }
            __syncthreads();
            gemm_tile<true>(smem, sbase, g_x16, g_wq16, b_qkv, nullptr,
                            (uint32_t*)g_qkv16, bm_i * 128, bn_i * 128, KD_, NQKV_);
            __threadfence();
            __syncthreads();
            if (tid == 0) atomicExch(&g1[bm_i * 24 + bn_i], 1u);
        } else if (t < (unsigned)(T_CVT + T_G1 + T_ATT)) {
            // attention tile
            unsigned a = t - (T_CVT + T_G1);
            int qb = (int)(a >> 5), b = (int)((a >> 4) & 1), h = (int)(a & 15);
            if (tid == 0) {
                int ct0 = (3 * h) >> 1;
                for (int rb = qb - 1; rb <= qb + 1; ++rb) {
                    if (rb < 0 || rb > 15) continue;
                    int base = (b * 16 + rb) * 24 + ct0;
                    spin_flag(&g1[base]);
                    spin_flag(&g1[base + 1]);
                }
                __threadfence();
            }
            __syncthreads();
            attn_tile(smem, sbase, g_qkv16, pmask, (uint32_t*)g_att16, b, h, qb * 128);
            __threadfence();
            __syncthreads();
            if (tid == 0) atomicAdd(&fa[b * 16 + qb], 1u);
        } else {
            // output projection tile
            unsigned g = t - (T_CVT + T_G1 + T_ATT);
            int j = (int)(g >> 3), bn_i = (int)(g & 7);
            int bm_i = ((j & 1) << 4) + (j >> 1);
            if (tid == 0) {
                while (((volatile unsigned*)fa)[bm_i] < 16u) __nanosleep(64);
                spin_flag(&fwo[2 * bn_i]);
                spin_flag(&fwo[2 * bn_i + 1]);
                __threadfence();
            }
            __syncthreads();
            gemm_tile<false>(smem, sbase, g_att16, g_wo16, b_o, out,
                             nullptr, bm_i * 128, bn_i * 128, KD_, E_);
        }
    }

    // ---- self-clean: last CTA resets g_sync for next launch/replay ----
    __threadfence();
    __syncthreads();
    if (tid == 0)
        s_t = (atomicAdd(&g_sync[SY_DONE], 1u) == (unsigned)(gridDim.x - 1)) ? 1u : 0u;
    __syncthreads();
    if (s_t) {
        for (int i = tid; i < SY_N; i += 256) g_sync[i] = 0u;
    }
}

// ---------------------------------------------------------------------------
// kernel_launch
// ---------------------------------------------------------------------------
extern "C" void kernel_launch(void* const* d_in, const int* in_sizes, int n_in,
                              void* d_out, int out_size)
{
    const float* x      = (const float*)d_in[0];
    const int*   pmask  = (const int*)d_in[1];
    const float* W_qkv  = (const float*)d_in[2];
    const float* b_qkv  = (const float*)d_in[3];
    const float* W_o    = (const float*)d_in[4];
    const float* b_o    = (const float*)d_in[5];
    float* out = (float*)d_out;

    static bool attr_done = false;
    if (!attr_done) {
        cudaFuncSetAttribute(mega, cudaFuncAttributeMaxDynamicSharedMemorySize, MEGA_SMEM);
        attr_done = true;
    }

    mega<<<MEGA_CTAS, 256, MEGA_SMEM>>>(x, W_qkv, W_o, b_qkv, b_o, pmask, out);
}

// round 12
// speedup vs baseline: 1.0190x; 1.0190x over previous
#include <cuda_runtime.h>
#include <cuda_fp16.h>
#include <cstdint>
#include <math.h>

// Problem constants
#define B_    2
#define L_    2048
#define E_    1024
#define H_    16
#define HD_   64
#define KD_   1024
#define NQKV_ 3072
#define ML_   (B_*L_)   // 4096

// ---------------- GEMM tiling (fp16 single product) ----------------
#define BM 128
#define BN 128
#define BK 64
#define ROWB 144
#define B_OFF   (128 * ROWB)
#define STAGEB  (256 * ROWB)        // 36864
#define GEMM_SMEM (2 * STAGEB)      // 73728

// ---------------- attention tiling ----------------
#define AROWB 144
#define QROWS 128
#define KROWS 192
#define S_Q  0
#define S_K  (S_Q + QROWS*AROWB)
#define S_V  (S_K + KROWS*AROWB)
#define S_OK (S_V + KROWS*AROWB)
#define ATTN_SMEM (S_OK + KROWS*4)  // 74496

#define MEGA_SMEM (ATTN_SMEM > GEMM_SMEM ? ATTN_SMEM : GEMM_SMEM)
#define MEGA_CTAS 296

// Ticket layout: converts (wq 48 | x 64 | wo 16) -> gemm1 -> attn -> gemm0
#define T_CVT  128
#define T_G1   768                  // 32 x 24
#define T_ATT  512                  // 16 qb x 2 b x 16 h
#define T_G0   256                  // 32 x 8
#define T_TOT  (T_CVT + T_G1 + T_ATT + T_G0)

// g_sync layout
#define SY_TICK 0
#define SY_G1   1                   // 768
#define SY_FA   769                 // 32
#define SY_FWQ  801                 // 48
#define SY_FX   849                 // 64
#define SY_FWO  913                 // 16
#define SY_DONE 929
#define SY_N    930

// ---------------- scratch ----------------
__device__ __half g_qkv16[(size_t)ML_ * NQKV_];
__device__ __half g_att16[(size_t)ML_ * E_];
__device__ __half g_x16[(size_t)ML_ * KD_];
__device__ __half g_wq16[(size_t)NQKV_ * KD_];
__device__ __half g_wo16[(size_t)E_ * E_];
__device__ unsigned g_sync[SY_N];   // zero-initialized; self-cleaned per launch

// ---------------- helpers ----------------
__device__ __forceinline__ uint32_t smem_u32(const void* p) {
    uint32_t a;
    asm("{ .reg .u64 t; cvta.to.shared.u64 t, %1; cvt.u32.u64 %0, t; }" : "=r"(a) : "l"(p));
    return a;
}
#define CP16(dst, src) \
    asm volatile("cp.async.cg.shared.global [%0], [%1], 16;" :: "r"(dst), "l"(src))
#define CP_COMMIT() asm volatile("cp.async.commit_group;" ::: "memory")
#define CP_WAIT(n)  asm volatile("cp.async.wait_group %0;" :: "n"(n) : "memory")

#define LDSM_X4(r0, r1, r2, r3, a) \
    asm volatile("ldmatrix.sync.aligned.m8n8.x4.shared.b16 {%0,%1,%2,%3}, [%4];" \
                 : "=r"(r0), "=r"(r1), "=r"(r2), "=r"(r3) : "r"(a))
#define LDSM_X4_T(r0, r1, r2, r3, a) \
    asm volatile("ldmatrix.sync.aligned.m8n8.x4.trans.shared.b16 {%0,%1,%2,%3}, [%4];" \
                 : "=r"(r0), "=r"(r1), "=r"(r2), "=r"(r3) : "r"(a))

__device__ __forceinline__ void mma_f16(float c[4], const uint32_t a[4],
                                        uint32_t b0, uint32_t b1) {
    asm volatile(
        "mma.sync.aligned.m16n8k16.row.col.f32.f16.f16.f32 "
        "{%0,%1,%2,%3}, {%4,%5,%6,%7}, {%8,%9}, {%0,%1,%2,%3};"
        : "+f"(c[0]), "+f"(c[1]), "+f"(c[2]), "+f"(c[3])
        : "r"(a[0]), "r"(a[1]), "r"(a[2]), "r"(a[3]), "r"(b0), "r"(b1));
}

__device__ __forceinline__ uint32_t pk_h2(float x, float y) {
    __half2 t = __floats2half2_rn(x, y);
    return *(uint32_t*)&t;
}

__device__ __forceinline__ void spin_flag(volatile unsigned* f) {
    while (*f == 0u) __nanosleep(64);
}

// ---------------------------------------------------------------------------
// One GEMM tile: C[bm:bm+128, bn:bn+128] = A*B^T + bias
// ---------------------------------------------------------------------------
template<bool F16OUT>
__device__ __forceinline__ void gemm_tile(
    char* smem, uint32_t sbase,
    const __half* __restrict__ A, const __half* __restrict__ Bm,
    const float* __restrict__ bias, float* __restrict__ Cf,
    uint32_t* __restrict__ Ch, int bm, int bn, int K, int N)
{
    const int tid  = threadIdx.x;
    const int lane = tid & 31;
    const int wid  = tid >> 5;
    const int warp_m = wid >> 1;
    const int warp_n = wid & 1;
    const int NT = K / BK;

    const int tr = tid >> 3;
    const int lc = tid & 7;
    const __half* Abase = A + (size_t)bm * K;
    const __half* Bbase = Bm + (size_t)bn * K;
    size_t offA[4];
    uint32_t dstA[4];
#pragma unroll
    for (int i = 0; i < 4; ++i) {
        int ra = i * 32 + tr;
        offA[i] = (size_t)ra * K + lc * 8;
        dstA[i] = (uint32_t)(ra * ROWB + lc * 16);
    }

    const uint32_t aOff = (uint32_t)((warp_m * 32 + (lane & 15)) * ROWB + (lane >> 4) * 16);
    const uint32_t bOff = (uint32_t)(B_OFF +
        (warp_n * 64 + ((lane >> 4) << 3) + (lane & 7)) * ROWB + ((lane >> 3) & 1) * 16);

    float acc[2][8][4];
#pragma unroll
    for (int mt = 0; mt < 2; ++mt)
#pragma unroll
        for (int nt = 0; nt < 8; ++nt)
#pragma unroll
            for (int j = 0; j < 4; ++j) acc[mt][nt][j] = 0.0f;

    {
        uint32_t sb = sbase;
#pragma unroll
        for (int i = 0; i < 4; ++i) {
            CP16(sb + dstA[i], Abase + offA[i]);
            CP16(sb + dstA[i] + B_OFF, Bbase + offA[i]);
        }
        CP_COMMIT();
    }

    for (int kt = 0; kt < NT; ++kt) {
        CP_WAIT(0);
        __syncthreads();
        if (kt + 1 < NT) {
            uint32_t sb = sbase + ((kt + 1) & 1) * STAGEB;
            int koff = (kt + 1) * BK;
#pragma unroll
            for (int i = 0; i < 4; ++i) {
                CP16(sb + dstA[i], Abase + offA[i] + koff);
                CP16(sb + dstA[i] + B_OFF, Bbase + offA[i] + koff);
            }
            CP_COMMIT();
        }

        const uint32_t st = sbase + (kt & 1) * STAGEB;
#pragma unroll
        for (int s = 0; s < 4; ++s) {
            uint32_t af[2][4], bf[8][2];
#pragma unroll
            for (int mt = 0; mt < 2; ++mt) {
                uint32_t a = st + aOff + mt * 16 * ROWB + s * 32;
                LDSM_X4(af[mt][0], af[mt][1], af[mt][2], af[mt][3], a);
            }
#pragma unroll
            for (int p = 0; p < 4; ++p) {
                uint32_t a = st + bOff + p * 16 * ROWB + s * 32;
                LDSM_X4(bf[2*p][0], bf[2*p][1], bf[2*p+1][0], bf[2*p+1][1], a);
            }
#pragma unroll
            for (int mt = 0; mt < 2; ++mt)
#pragma unroll
                for (int nt = 0; nt < 8; ++nt)
                    mma_f16(acc[mt][nt], af[mt], bf[nt][0], bf[nt][1]);
        }
        __syncthreads();
    }

    const int r0 = bm + warp_m * 32 + (lane >> 2);
    const int c0 = bn + warp_n * 64 + (lane & 3) * 2;
#pragma unroll
    for (int mt = 0; mt < 2; ++mt) {
#pragma unroll
        for (int nt = 0; nt < 8; ++nt) {
            int col = c0 + nt * 8;
            float bx = bias[col], by = bias[col + 1];
            float vx0 = acc[mt][nt][0] + bx, vy0 = acc[mt][nt][1] + by;
            float vx1 = acc[mt][nt][2] + bx, vy1 = acc[mt][nt][3] + by;
            int ra = r0 + mt * 16, rb = ra + 8;
            if (F16OUT) {
                Ch[(size_t)ra * (N >> 1) + (col >> 1)] = pk_h2(vx0, vy0);
                Ch[(size_t)rb * (N >> 1) + (col >> 1)] = pk_h2(vx1, vy1);
            } else {
                *(float2*)(Cf + (size_t)ra * N + col) = make_float2(vx0, vy0);
                *(float2*)(Cf + (size_t)rb * N + col) = make_float2(vx1, vy1);
            }
        }
    }
}

// ---------------------------------------------------------------------------
// One band-skipping attention tile (b, h, q0..q0+127), 256 threads.
// ---------------------------------------------------------------------------
__device__ __forceinline__ void attn_tile(
    char* smem, uint32_t sb,
    const __half* __restrict__ qkv, const int* __restrict__ pmask,
    uint32_t* __restrict__ Oh, int b, int h, int q0)
{
    const int tid = threadIdx.x, lane = tid & 31, w = tid >> 5;

    for (int i = tid; i < QROWS * 8; i += 256) {
        int r = i >> 3, c = i & 7;
        size_t g = (size_t)(b * L_ + q0 + r) * NQKV_ + h * 192 + c * 8;
        *(uint4*)(smem + S_Q + r * AROWB + c * 16) = *(const uint4*)(qkv + g);
    }
    for (int i = tid; i < KROWS * 8; i += 256) {
        int r = i >> 3, c = i & 7;
        int pos = q0 - 32 + r;
        uint4 kv = make_uint4(0, 0, 0, 0), vv = make_uint4(0, 0, 0, 0);
        if (pos >= 0 && pos < L_) {
            size_t g = (size_t)(b * L_ + pos) * NQKV_ + h * 192 + c * 8;
            kv = *(const uint4*)(qkv + g + 64);
            vv = *(const uint4*)(qkv + g + 128);
        }
        *(uint4*)(smem + S_K + r * AROWB + c * 16) = kv;
        *(uint4*)(smem + S_V + r * AROWB + c * 16) = vv;
    }
    if (tid < KROWS) {
        int pos = q0 - 32 + tid;
        int ok = (pos >= 0 && pos < L_) ? (pmask[b * L_ + pos] != 0) : 0;
        ((int*)(smem + S_OK))[tid] = ok;
    }
    __syncthreads();
    const int* okk = (const int*)(smem + S_OK);

    float S[10][4];
#pragma unroll
    for (int i = 0; i < 10; ++i)
#pragma unroll
        for (int j = 0; j < 4; ++j) S[i][j] = 0.0f;

    uint32_t qf[4][4];
    {
        uint32_t aoff = (uint32_t)((w * 16 + (lane & 15)) * AROWB + (lane >> 4) * 16);
#pragma unroll
        for (int ks = 0; ks < 4; ++ks)
            LDSM_X4(qf[ks][0], qf[ks][1], qf[ks][2], qf[ks][3], sb + S_Q + aoff + ks * 32);
    }
    {
        uint32_t boff = (uint32_t)(((((lane >> 4) << 3) + (lane & 7)) * AROWB) + ((lane >> 3) & 1) * 16);
#pragma unroll
        for (int kbl = 0; kbl < 5; ++kbl) {
            uint32_t base = boff + (w + kbl) * 16 * AROWB;
#pragma unroll
            for (int ks = 0; ks < 4; ++ks) {
                uint32_t b0, b1, b2, b3;
                LDSM_X4(b0, b1, b2, b3, sb + S_K + base + ks * 32);
                mma_f16(S[2 * kbl],     qf[ks], b0, b1);
                mma_f16(S[2 * kbl + 1], qf[ks], b2, b3);
            }
        }
    }

    const int qlo = w * 16 + (lane >> 2);
    const float scale = 0.125f;
    const float NEGS = -12500.0f;
    float mlo = -3.0e38f, mhi = -3.0e38f;
#pragma unroll
    for (int nbl = 0; nbl < 10; ++nbl) {
        int kbl = nbl >> 1, grp = nbl & 1;
#pragma unroll
        for (int p = 0; p < 2; ++p) {
            int j = (w + kbl) * 16 + grp * 8 + (lane & 3) * 2 + p;
            float s0 = S[nbl][p];
            int d0 = j - qlo;
            s0 = (d0 >= 0 && d0 <= 64) ? (okk[j] ? s0 * scale : NEGS) : -3.0e38f;
            S[nbl][p] = s0;
            mlo = fmaxf(mlo, s0);
            float s1 = S[nbl][2 + p];
            int d1 = j - (qlo + 8);
            s1 = (d1 >= 0 && d1 <= 64) ? (okk[j] ? s1 * scale : NEGS) : -3.0e38f;
            S[nbl][2 + p] = s1;
            mhi = fmaxf(mhi, s1);
        }
    }
#pragma unroll
    for (int o = 1; o <= 2; o <<= 1) {
        mlo = fmaxf(mlo, __shfl_xor_sync(0xffffffffu, mlo, o));
        mhi = fmaxf(mhi, __shfl_xor_sync(0xffffffffu, mhi, o));
    }
    float slo = 0.f, shi = 0.f;
#pragma unroll
    for (int nbl = 0; nbl < 10; ++nbl) {
#pragma unroll
        for (int p = 0; p < 2; ++p) {
            float e0 = __expf(S[nbl][p] - mlo);     S[nbl][p] = e0;     slo += e0;
            float e1 = __expf(S[nbl][2 + p] - mhi); S[nbl][2 + p] = e1; shi += e1;
        }
    }
#pragma unroll
    for (int o = 1; o <= 2; o <<= 1) {
        slo += __shfl_xor_sync(0xffffffffu, slo, o);
        shi += __shfl_xor_sync(0xffffffffu, shi, o);
    }
    const float invlo = 1.0f / slo;
    const float invhi = 1.0f / shi;

    uint32_t pf[5][4];
#pragma unroll
    for (int kbl = 0; kbl < 5; ++kbl) {
        pf[kbl][0] = pk_h2(S[2 * kbl][0] * invlo,     S[2 * kbl][1] * invlo);
        pf[kbl][1] = pk_h2(S[2 * kbl][2] * invhi,     S[2 * kbl][3] * invhi);
        pf[kbl][2] = pk_h2(S[2 * kbl + 1][0] * invlo, S[2 * kbl + 1][1] * invlo);
        pf[kbl][3] = pk_h2(S[2 * kbl + 1][2] * invhi, S[2 * kbl + 1][3] * invhi);
    }

    float O[8][4];
#pragma unroll
    for (int i = 0; i < 8; ++i)
#pragma unroll
        for (int j = 0; j < 4; ++j) O[i][j] = 0.0f;

    {
        uint32_t voff = (uint32_t)((lane & 15) * AROWB + (lane >> 4) * 16);
#pragma unroll
        for (int kbl = 0; kbl < 5; ++kbl) {
            uint32_t base = voff + (w + kbl) * 16 * AROWB;
#pragma unroll
            for (int db = 0; db < 4; ++db) {
                uint32_t v0, v1, v2, v3;
                LDSM_X4_T(v0, v1, v2, v3, sb + S_V + base + db * 32);
                mma_f16(O[2 * db],     pf[kbl], v0, v1);
                mma_f16(O[2 * db + 1], pf[kbl], v2, v3);
            }
        }
    }

    const size_t rowlo = (size_t)(b * L_ + q0 + qlo);
    const size_t rowhi = rowlo + 8;
#pragma unroll
    for (int nb = 0; nb < 8; ++nb) {
        int col = h * 64 + nb * 8 + (lane & 3) * 2;
        Oh[rowlo * (E_ / 2) + (col >> 1)] = pk_h2(O[nb][0], O[nb][1]);
        Oh[rowhi * (E_ / 2) + (col >> 1)] = pk_h2(O[nb][2], O[nb][3]);
    }
}

// ---------------------------------------------------------------------------
// MLP-unrolled convert of one 64x1024 fp32 chunk (16384 float4 -> 8192 uint4).
// 4 passes of 8-wide batched loads (16 outstanding 16B loads per thread).
// ---------------------------------------------------------------------------
__device__ __forceinline__ void convert_chunk(
    const float4* __restrict__ src, uint4* __restrict__ dst, int tid)
{
#pragma unroll
    for (int p = 0; p < 4; ++p) {
        float4 a[8], b[8];
#pragma unroll
        for (int j = 0; j < 8; ++j) {
            int idx = (p * 8 + j) * 256 + tid;       // uint4 index, 0..8191
            a[j] = src[2 * idx];
            b[j] = src[2 * idx + 1];
        }
#pragma unroll
        for (int j = 0; j < 8; ++j) {
            int idx = (p * 8 + j) * 256 + tid;
            dst[idx] = make_uint4(pk_h2(a[j].x, a[j].y), pk_h2(a[j].z, a[j].w),
                                  pk_h2(b[j].x, b[j].y), pk_h2(b[j].z, b[j].w));
        }
    }
}

// ---------------------------------------------------------------------------
// Fully fused pipeline: converts -> gemm1 -> attn -> gemm0, flag-gated.
// Self-cleans g_sync at the end (last CTA) for graph replay.
// ---------------------------------------------------------------------------
__global__ __launch_bounds__(256, 2) void mega(
    const float* __restrict__ x, const float* __restrict__ W_qkv,
    const float* __restrict__ W_o,
    const float* __restrict__ b_qkv, const float* __restrict__ b_o,
    const int* __restrict__ pmask, float* __restrict__ out)
{
    extern __shared__ char smem[];
    __shared__ unsigned s_t;
    const uint32_t sbase = smem_u32(smem);
    const int tid = threadIdx.x;
    unsigned* tick = &g_sync[SY_TICK];
    unsigned* g1   = &g_sync[SY_G1];
    unsigned* fa   = &g_sync[SY_FA];
    unsigned* fwq  = &g_sync[SY_FWQ];
    unsigned* fx   = &g_sync[SY_FX];
    unsigned* fwo  = &g_sync[SY_FWO];

    for (;;) {
        __syncthreads();
        if (tid == 0) s_t = atomicAdd(tick, 1u);
        __syncthreads();
        const unsigned t = s_t;
        if (t >= (unsigned)T_TOT) break;

        if (t < (unsigned)T_CVT) {
            // convert one 64-row x 1024-col fp32 chunk to fp16 (MLP-unrolled)
            const float4* src;
            uint4* dst;
            unsigned* flag;
            if (t < 48u) {            // W_qkv chunks (needed by all gemm1)
                src  = (const float4*)W_qkv + (size_t)t * 16384;
                dst  = (uint4*)g_wq16 + (size_t)t * 8192;
                flag = &fwq[t];
            } else if (t < 112u) {    // x chunks
                unsigned c = t - 48u;
                src  = (const float4*)x + (size_t)c * 16384;
                dst  = (uint4*)g_x16 + (size_t)c * 8192;
                flag = &fx[c];
            } else {                  // W_o chunks
                unsigned c = t - 112u;
                src  = (const float4*)W_o + (size_t)c * 16384;
                dst  = (uint4*)g_wo16 + (size_t)c * 8192;
                flag = &fwo[c];
            }
            convert_chunk(src, dst, tid);
            __threadfence();
            __syncthreads();
            if (tid == 0) atomicExch(flag, 1u);
        } else if (t < (unsigned)(T_CVT + T_G1)) {
            // QKV projection tile; batches interleaved so early rows finish first
            unsigned u = t - T_CVT;
            int i = (int)u / 24, bn_i = (int)u % 24;
            int bm_i = ((i & 1) << 4) + (i >> 1);
            if (tid == 0) {
                spin_flag(&fwq[2 * bn_i]);
                spin_flag(&fwq[2 * bn_i + 1]);
                spin_flag(&fx[2 * bm_i]);
                spin_flag(&fx[2 * bm_i + 1]);
                __threadfence();
            }
            __syncthreads();
            gemm_tile<true>(smem, sbase, g_x16, g_wq16, b_qkv, nullptr,
                            (uint32_t*)g_qkv16, bm_i * 128, bn_i * 128, KD_, NQKV_);
            __threadfence();
            __syncthreads();
            if (tid == 0) atomicExch(&g1[bm_i * 24 + bn_i], 1u);
        } else if (t < (unsigned)(T_CVT + T_G1 + T_ATT)) {
            // attention tile
            unsigned a = t - (T_CVT + T_G1);
            int qb = (int)(a >> 5), b = (int)((a >> 4) & 1), h = (int)(a & 15);
            if (tid == 0) {
                int ct0 = (3 * h) >> 1;
                for (int rb = qb - 1; rb <= qb + 1; ++rb) {
                    if (rb < 0 || rb > 15) continue;
                    int base = (b * 16 + rb) * 24 + ct0;
                    spin_flag(&g1[base]);
                    spin_flag(&g1[base + 1]);
                }
                __threadfence();
            }
            __syncthreads();
            attn_tile(smem, sbase, g_qkv16, pmask, (uint32_t*)g_att16, b, h, qb * 128);
            __threadfence();
            __syncthreads();
            if (tid == 0) atomicAdd(&fa[b * 16 + qb], 1u);
        } else {
            // output projection tile
            unsigned g = t - (T_CVT + T_G1 + T_ATT);
            int j = (int)(g >> 3), bn_i = (int)(g & 7);
            int bm_i = ((j & 1) << 4) + (j >> 1);
            if (tid == 0) {
                while (((volatile unsigned*)fa)[bm_i] < 16u) __nanosleep(64);
                spin_flag(&fwo[2 * bn_i]);
                spin_flag(&fwo[2 * bn_i + 1]);
                __threadfence();
            }
            __syncthreads();
            gemm_tile<false>(smem, sbase, g_att16, g_wo16, b_o, out,
                             nullptr, bm_i * 128, bn_i * 128, KD_, E_);
        }
    }

    // ---- self-clean: last CTA resets g_sync for next launch/replay ----
    __threadfence();
    __syncthreads();
    if (tid == 0)
        s_t = (atomicAdd(&g_sync[SY_DONE], 1u) == (unsigned)(gridDim.x - 1)) ? 1u : 0u;
    __syncthreads();
    if (s_t) {
        for (int i = tid; i < SY_N; i += 256) g_sync[i] = 0u;
    }
}

// ---------------------------------------------------------------------------
// kernel_launch
// ---------------------------------------------------------------------------
extern "C" void kernel_launch(void* const* d_in, const int* in_sizes, int n_in,
                              void* d_out, int out_size)
{
    const float* x      = (const float*)d_in[0];
    const int*   pmask  = (const int*)d_in[1];
    const float* W_qkv  = (const float*)d_in[2];
    const float* b_qkv  = (const float*)d_in[3];
    const float* W_o    = (const float*)d_in[4];
    const float* b_o    = (const float*)d_in[5];
    float* out = (float*)d_out;

    static bool attr_done = false;
    if (!attr_done) {
        cudaFuncSetAttribute(mega, cudaFuncAttributeMaxDynamicSharedMemorySize, MEGA_SMEM);
        attr_done = true;
    }

    mega<<<MEGA_CTAS, 256, MEGA_SMEM>>>(x, W_qkv, W_o, b_qkv, b_o, pmask, out);
}

// round 13
// speedup vs baseline: 1.0229x; 1.0038x over previous
#include <cuda_runtime.h>
#include <cuda_fp16.h>
#include <cstdint>
#include <math.h>

// Problem constants
#define B_    2
#define L_    2048
#define E_    1024
#define H_    16
#define HD_   64
#define KD_   1024
#define NQKV_ 3072
#define ML_   (B_*L_)   // 4096

// ---------------- GEMM tiling (fp16 single product) ----------------
#define BM 128
#define BN 128
#define BK 64
#define ROWB 144
#define B_OFF   (128 * ROWB)
#define STAGEB  (256 * ROWB)        // 36864
#define GEMM_SMEM (2 * STAGEB)      // 73728

// ---------------- attention tiling ----------------
#define AROWB 144
#define QROWS 128
#define KROWS 192
#define S_Q  0
#define S_K  (S_Q + QROWS*AROWB)
#define S_V  (S_K + KROWS*AROWB)
#define S_OK (S_V + KROWS*AROWB)
#define ATTN_SMEM (S_OK + KROWS*4)  // 74496

#define MEGA_SMEM (ATTN_SMEM > GEMM_SMEM ? ATTN_SMEM : GEMM_SMEM)
#define MEGA_CTAS 296

// Ticket layout
#define T_G1   768                  // gemm1 tiles (32 x 24)
#define T_ATT  512                  // attention tiles (16 qb x 2 b x 16 h)
#define T_G0   256                  // gemm0 tiles (32 x 8)
#define T_TOT  (T_G1 + T_ATT + T_G0)

// ---------------- scratch ----------------
__device__ __half g_qkv16[(size_t)ML_ * NQKV_];
__device__ __half g_att16[(size_t)ML_ * E_];
__device__ __half g_x16[(size_t)ML_ * KD_];
__device__ __half g_wq16[(size_t)NQKV_ * KD_];
__device__ __half g_wo16[(size_t)E_ * E_];
// [0] tick, [1..768] g1 flags, [769..800] fa flags
__device__ unsigned g_sync[1 + 768 + 32];

// ---------------- helpers ----------------
__device__ __forceinline__ uint32_t smem_u32(const void* p) {
    uint32_t a;
    asm("{ .reg .u64 t; cvta.to.shared.u64 t, %1; cvt.u32.u64 %0, t; }" : "=r"(a) : "l"(p));
    return a;
}
#define CP16(dst, src) \
    asm volatile("cp.async.cg.shared.global [%0], [%1], 16;" :: "r"(dst), "l"(src))
#define CP_COMMIT() asm volatile("cp.async.commit_group;" ::: "memory")
#define CP_WAIT(n)  asm volatile("cp.async.wait_group %0;" :: "n"(n) : "memory")

#define LDSM_X4(r0, r1, r2, r3, a) \
    asm volatile("ldmatrix.sync.aligned.m8n8.x4.shared.b16 {%0,%1,%2,%3}, [%4];" \
                 : "=r"(r0), "=r"(r1), "=r"(r2), "=r"(r3) : "r"(a))
#define LDSM_X4_T(r0, r1, r2, r3, a) \
    asm volatile("ldmatrix.sync.aligned.m8n8.x4.trans.shared.b16 {%0,%1,%2,%3}, [%4];" \
                 : "=r"(r0), "=r"(r1), "=r"(r2), "=r"(r3) : "r"(a))

__device__ __forceinline__ void mma_f16(float c[4], const uint32_t a[4],
                                        uint32_t b0, uint32_t b1) {
    asm volatile(
        "mma.sync.aligned.m16n8k16.row.col.f32.f16.f16.f32 "
        "{%0,%1,%2,%3}, {%4,%5,%6,%7}, {%8,%9}, {%0,%1,%2,%3};"
        : "+f"(c[0]), "+f"(c[1]), "+f"(c[2]), "+f"(c[3])
        : "r"(a[0]), "r"(a[1]), "r"(a[2]), "r"(a[3]), "r"(b0), "r"(b1));
}

__device__ __forceinline__ uint32_t pk_h2(float x, float y) {
    __half2 t = __floats2half2_rn(x, y);
    return *(uint32_t*)&t;
}

// ---------------------------------------------------------------------------
// One GEMM tile: C[bm:bm+128, bn:bn+128] = A*B^T + bias
// Single barrier per K-iteration: the top-of-loop CP_WAIT + syncthreads
// already orders all threads' compute of kt before any kt+2 load lands.
// ---------------------------------------------------------------------------
template<bool F16OUT>
__device__ __forceinline__ void gemm_tile(
    char* smem, uint32_t sbase,
    const __half* __restrict__ A, const __half* __restrict__ Bm,
    const float* __restrict__ bias, float* __restrict__ Cf,
    uint32_t* __restrict__ Ch, int bm, int bn, int K, int N)
{
    const int tid  = threadIdx.x;
    const int lane = tid & 31;
    const int wid  = tid >> 5;
    const int warp_m = wid >> 1;
    const int warp_n = wid & 1;
    const int NT = K / BK;

    const int tr = tid >> 3;
    const int lc = tid & 7;
    const __half* Abase = A + (size_t)bm * K;
    const __half* Bbase = Bm + (size_t)bn * K;
    size_t offA[4];
    uint32_t dstA[4];
#pragma unroll
    for (int i = 0; i < 4; ++i) {
        int ra = i * 32 + tr;
        offA[i] = (size_t)ra * K + lc * 8;
        dstA[i] = (uint32_t)(ra * ROWB + lc * 16);
    }

    const uint32_t aOff = (uint32_t)((warp_m * 32 + (lane & 15)) * ROWB + (lane >> 4) * 16);
    const uint32_t bOff = (uint32_t)(B_OFF +
        (warp_n * 64 + ((lane >> 4) << 3) + (lane & 7)) * ROWB + ((lane >> 3) & 1) * 16);

    float acc[2][8][4];
#pragma unroll
    for (int mt = 0; mt < 2; ++mt)
#pragma unroll
        for (int nt = 0; nt < 8; ++nt)
#pragma unroll
            for (int j = 0; j < 4; ++j) acc[mt][nt][j] = 0.0f;

    {
        uint32_t sb = sbase;
#pragma unroll
        for (int i = 0; i < 4; ++i) {
            CP16(sb + dstA[i], Abase + offA[i]);
            CP16(sb + dstA[i] + B_OFF, Bbase + offA[i]);
        }
        CP_COMMIT();
    }

    for (int kt = 0; kt < NT; ++kt) {
        CP_WAIT(0);
        __syncthreads();
        if (kt + 1 < NT) {
            uint32_t sb = sbase + ((kt + 1) & 1) * STAGEB;
            int koff = (kt + 1) * BK;
#pragma unroll
            for (int i = 0; i < 4; ++i) {
                CP16(sb + dstA[i], Abase + offA[i] + koff);
                CP16(sb + dstA[i] + B_OFF, Bbase + offA[i] + koff);
            }
            CP_COMMIT();
        }

        const uint32_t st = sbase + (kt & 1) * STAGEB;
#pragma unroll
        for (int s = 0; s < 4; ++s) {
            uint32_t af[2][4], bf[8][2];
#pragma unroll
            for (int mt = 0; mt < 2; ++mt) {
                uint32_t a = st + aOff + mt * 16 * ROWB + s * 32;
                LDSM_X4(af[mt][0], af[mt][1], af[mt][2], af[mt][3], a);
            }
#pragma unroll
            for (int p = 0; p < 4; ++p) {
                uint32_t a = st + bOff + p * 16 * ROWB + s * 32;
                LDSM_X4(bf[2*p][0], bf[2*p][1], bf[2*p+1][0], bf[2*p+1][1], a);
            }
#pragma unroll
            for (int mt = 0; mt < 2; ++mt)
#pragma unroll
                for (int nt = 0; nt < 8; ++nt)
                    mma_f16(acc[mt][nt], af[mt], bf[nt][0], bf[nt][1]);
        }
        // no end-of-loop barrier: next iteration's top sync provides ordering
    }

    const int r0 = bm + warp_m * 32 + (lane >> 2);
    const int c0 = bn + warp_n * 64 + (lane & 3) * 2;
#pragma unroll
    for (int mt = 0; mt < 2; ++mt) {
#pragma unroll
        for (int nt = 0; nt < 8; ++nt) {
            int col = c0 + nt * 8;
            float bx = bias[col], by = bias[col + 1];
            float vx0 = acc[mt][nt][0] + bx, vy0 = acc[mt][nt][1] + by;
            float vx1 = acc[mt][nt][2] + bx, vy1 = acc[mt][nt][3] + by;
            int ra = r0 + mt * 16, rb = ra + 8;
            if (F16OUT) {
                Ch[(size_t)ra * (N >> 1) + (col >> 1)] = pk_h2(vx0, vy0);
                Ch[(size_t)rb * (N >> 1) + (col >> 1)] = pk_h2(vx1, vy1);
            } else {
                *(float2*)(Cf + (size_t)ra * N + col) = make_float2(vx0, vy0);
                *(float2*)(Cf + (size_t)rb * N + col) = make_float2(vx1, vy1);
            }
        }
    }
}

// ---------------------------------------------------------------------------
// One band-skipping attention tile (b, h, q0..q0+127), 256 threads.
// ---------------------------------------------------------------------------
__device__ __forceinline__ void attn_tile(
    char* smem, uint32_t sb,
    const __half* __restrict__ qkv, const int* __restrict__ pmask,
    uint32_t* __restrict__ Oh, int b, int h, int q0)
{
    const int tid = threadIdx.x, lane = tid & 31, w = tid >> 5;

    for (int i = tid; i < QROWS * 8; i += 256) {
        int r = i >> 3, c = i & 7;
        size_t g = (size_t)(b * L_ + q0 + r) * NQKV_ + h * 192 + c * 8;
        *(uint4*)(smem + S_Q + r * AROWB + c * 16) = *(const uint4*)(qkv + g);
    }
    for (int i = tid; i < KROWS * 8; i += 256) {
        int r = i >> 3, c = i & 7;
        int pos = q0 - 32 + r;
        uint4 kv = make_uint4(0, 0, 0, 0), vv = make_uint4(0, 0, 0, 0);
        if (pos >= 0 && pos < L_) {
            size_t g = (size_t)(b * L_ + pos) * NQKV_ + h * 192 + c * 8;
            kv = *(const uint4*)(qkv + g + 64);
            vv = *(const uint4*)(qkv + g + 128);
        }
        *(uint4*)(smem + S_K + r * AROWB + c * 16) = kv;
        *(uint4*)(smem + S_V + r * AROWB + c * 16) = vv;
    }
    if (tid < KROWS) {
        int pos = q0 - 32 + tid;
        int ok = (pos >= 0 && pos < L_) ? (pmask[b * L_ + pos] != 0) : 0;
        ((int*)(smem + S_OK))[tid] = ok;
    }
    __syncthreads();
    const int* okk = (const int*)(smem + S_OK);

    float S[10][4];
#pragma unroll
    for (int i = 0; i < 10; ++i)
#pragma unroll
        for (int j = 0; j < 4; ++j) S[i][j] = 0.0f;

    uint32_t qf[4][4];
    {
        uint32_t aoff = (uint32_t)((w * 16 + (lane & 15)) * AROWB + (lane >> 4) * 16);
#pragma unroll
        for (int ks = 0; ks < 4; ++ks)
            LDSM_X4(qf[ks][0], qf[ks][1], qf[ks][2], qf[ks][3], sb + S_Q + aoff + ks * 32);
    }
    {
        uint32_t boff = (uint32_t)(((((lane >> 4) << 3) + (lane & 7)) * AROWB) + ((lane >> 3) & 1) * 16);
#pragma unroll
        for (int kbl = 0; kbl < 5; ++kbl) {
            uint32_t base = boff + (w + kbl) * 16 * AROWB;
#pragma unroll
            for (int ks = 0; ks < 4; ++ks) {
                uint32_t b0, b1, b2, b3;
                LDSM_X4(b0, b1, b2, b3, sb + S_K + base + ks * 32);
                mma_f16(S[2 * kbl],     qf[ks], b0, b1);
                mma_f16(S[2 * kbl + 1], qf[ks], b2, b3);
            }
        }
    }

    const int qlo = w * 16 + (lane >> 2);
    const float scale = 0.125f;
    const float NEGS = -12500.0f;
    float mlo = -3.0e38f, mhi = -3.0e38f;
#pragma unroll
    for (int nbl = 0; nbl < 10; ++nbl) {
        int kbl = nbl >> 1, grp = nbl & 1;
#pragma unroll
        for (int p = 0; p < 2; ++p) {
            int j = (w + kbl) * 16 + grp * 8 + (lane & 3) * 2 + p;
            float s0 = S[nbl][p];
            int d0 = j - qlo;
            s0 = (d0 >= 0 && d0 <= 64) ? (okk[j] ? s0 * scale : NEGS) : -3.0e38f;
            S[nbl][p] = s0;
            mlo = fmaxf(mlo, s0);
            float s1 = S[nbl][2 + p];
            int d1 = j - (qlo + 8);
            s1 = (d1 >= 0 && d1 <= 64) ? (okk[j] ? s1 * scale : NEGS) : -3.0e38f;
            S[nbl][2 + p] = s1;
            mhi = fmaxf(mhi, s1);
        }
    }
#pragma unroll
    for (int o = 1; o <= 2; o <<= 1) {
        mlo = fmaxf(mlo, __shfl_xor_sync(0xffffffffu, mlo, o));
        mhi = fmaxf(mhi, __shfl_xor_sync(0xffffffffu, mhi, o));
    }
    float slo = 0.f, shi = 0.f;
#pragma unroll
    for (int nbl = 0; nbl < 10; ++nbl) {
#pragma unroll
        for (int p = 0; p < 2; ++p) {
            float e0 = __expf(S[nbl][p] - mlo);     S[nbl][p] = e0;     slo += e0;
            float e1 = __expf(S[nbl][2 + p] - mhi); S[nbl][2 + p] = e1; shi += e1;
        }
    }
#pragma unroll
    for (int o = 1; o <= 2; o <<= 1) {
        slo += __shfl_xor_sync(0xffffffffu, slo, o);
        shi += __shfl_xor_sync(0xffffffffu, shi, o);
    }
    const float invlo = 1.0f / slo;
    const float invhi = 1.0f / shi;

    uint32_t pf[5][4];
#pragma unroll
    for (int kbl = 0; kbl < 5; ++kbl) {
        pf[kbl][0] = pk_h2(S[2 * kbl][0] * invlo,     S[2 * kbl][1] * invlo);
        pf[kbl][1] = pk_h2(S[2 * kbl][2] * invhi,     S[2 * kbl][3] * invhi);
        pf[kbl][2] = pk_h2(S[2 * kbl + 1][0] * invlo, S[2 * kbl + 1][1] * invlo);
        pf[kbl][3] = pk_h2(S[2 * kbl + 1][2] * invhi, S[2 * kbl + 1][3] * invhi);
    }

    float O[8][4];
#pragma unroll
    for (int i = 0; i < 8; ++i)
#pragma unroll
        for (int j = 0; j < 4; ++j) O[i][j] = 0.0f;

    {
        uint32_t voff = (uint32_t)((lane & 15) * AROWB + (lane >> 4) * 16);
#pragma unroll
        for (int kbl = 0; kbl < 5; ++kbl) {
            uint32_t base = voff + (w + kbl) * 16 * AROWB;
#pragma unroll
            for (int db = 0; db < 4; ++db) {
                uint32_t v0, v1, v2, v3;
                LDSM_X4_T(v0, v1, v2, v3, sb + S_V + base + db * 32);
                mma_f16(O[2 * db],     pf[kbl], v0, v1);
                mma_f16(O[2 * db + 1], pf[kbl], v2, v3);
            }
        }
    }

    const size_t rowlo = (size_t)(b * L_ + q0 + qlo);
    const size_t rowhi = rowlo + 8;
#pragma unroll
    for (int nb = 0; nb < 8; ++nb) {
        int col = h * 64 + nb * 8 + (lane & 3) * 2;
        Oh[rowlo * (E_ / 2) + (col >> 1)] = pk_h2(O[nb][0], O[nb][1]);
        Oh[rowhi * (E_ / 2) + (col >> 1)] = pk_h2(O[nb][2], O[nb][3]);
    }
}

// ---------------------------------------------------------------------------
// Fused pipeline kernel: gemm1 -> attn -> gemm0, flag-gated work stealing.
// ---------------------------------------------------------------------------
__global__ __launch_bounds__(256, 2) void mega(
    const __half* __restrict__ x16, const __half* __restrict__ wq16,
    const float* __restrict__ b_qkv, __half* __restrict__ qkv16,
    const int* __restrict__ pmask, __half* __restrict__ att16,
    const __half* __restrict__ wo16, const float* __restrict__ b_o,
    float* __restrict__ out)
{
    extern __shared__ char smem[];
    __shared__ unsigned s_t;
    const uint32_t sbase = smem_u32(smem);
    unsigned* tick = &g_sync[0];
    unsigned* g1   = &g_sync[1];
    unsigned* fa   = &g_sync[769];

    for (;;) {
        __syncthreads();
        if (threadIdx.x == 0) s_t = atomicAdd(tick, 1u);
        __syncthreads();
        const unsigned t = s_t;
        if (t >= (unsigned)T_TOT) break;

        if (t < (unsigned)T_G1) {
            // QKV projection tile; batches interleaved so early rows finish first
            int i = (int)t / 24, bn_i = (int)t % 24;
            int bm_i = ((i & 1) << 4) + (i >> 1);
            gemm_tile<true>(smem, sbase, x16, wq16, b_qkv, nullptr,
                            (uint32_t*)qkv16, bm_i * 128, bn_i * 128, KD_, NQKV_);
            __threadfence();
            __syncthreads();
            if (threadIdx.x == 0) atomicExch(&g1[bm_i * 24 + bn_i], 1u);
        } else if (t < (unsigned)(T_G1 + T_ATT)) {
            // attention tile (qb-major so row blocks complete early)
            unsigned a = t - T_G1;
            int qb = (int)(a >> 5), b = (int)((a >> 4) & 1), h = (int)(a & 15);
            if (threadIdx.x == 0) {
                int ct0 = (3 * h) >> 1;
                for (int rb = qb - 1; rb <= qb + 1; ++rb) {
                    if (rb < 0 || rb > 15) continue;
                    int base = (b * 16 + rb) * 24 + ct0;
                    while (((volatile unsigned*)g1)[base] == 0u) __nanosleep(64);
                    while (((volatile unsigned*)g1)[base + 1] == 0u) __nanosleep(64);
                }
                __threadfence();
            }
            __syncthreads();
            attn_tile(smem, sbase, qkv16, pmask, (uint32_t*)att16, b, h, qb * 128);
            __threadfence();
            __syncthreads();
            if (threadIdx.x == 0) atomicAdd(&fa[b * 16 + qb], 1u);
        } else {
            // output projection tile
            unsigned g = t - (T_G1 + T_ATT);
            int j = (int)(g >> 3), bn_i = (int)(g & 7);
            int bm_i = ((j & 1) << 4) + (j >> 1);
            if (threadIdx.x == 0) {
                while (((volatile unsigned*)fa)[bm_i] < 16u) __nanosleep(64);
                __threadfence();
            }
            __syncthreads();
            gemm_tile<false>(smem, sbase, att16, wo16, b_o, out,
                             nullptr, bm_i * 128, bn_i * 128, KD_, E_);
        }
    }
}

// ---------------------------------------------------------------------------
// fp32 -> fp16 converts (one launch) + sync-state reset
// ---------------------------------------------------------------------------
__global__ __launch_bounds__(256) void tohalf3(
    const float4* __restrict__ s0, uint2* __restrict__ d0, int n0,
    const float4* __restrict__ s1, uint2* __restrict__ d1, int n1,
    const float4* __restrict__ s2, uint2* __restrict__ d2, int n2,
    unsigned* __restrict__ sync)
{
    int i = blockIdx.x * blockDim.x + threadIdx.x;
    if (i < 1 + 768 + 32) sync[i] = 0;
    const float4* s; uint2* d;
    if (i < n0)           { s = s0 + i; d = d0 + i; }
    else if (i < n0 + n1) { s = s1 + (i - n0); d = d1 + (i - n0); }
    else if (i < n0 + n1 + n2) { s = s2 + (i - n0 - n1); d = d2 + (i - n0 - n1); }
    else return;
    float4 v = *s;
    *d = make_uint2(pk_h2(v.x, v.y), pk_h2(v.z, v.w));
}

// ---------------------------------------------------------------------------
// kernel_launch
// ---------------------------------------------------------------------------
extern "C" void kernel_launch(void* const* d_in, const int* in_sizes, int n_in,
                              void* d_out, int out_size)
{
    const float* x      = (const float*)d_in[0];
    const int*   pmask  = (const int*)d_in[1];
    const float* W_qkv  = (const float*)d_in[2];
    const float* b_qkv  = (const float*)d_in[3];
    const float* W_o    = (const float*)d_in[4];
    const float* b_o    = (const float*)d_in[5];
    float* out = (float*)d_out;

    __half *qkv16, *att16, *x16, *wq16, *wo16;
    unsigned* syncp;
    cudaGetSymbolAddress((void**)&qkv16, g_qkv16);
    cudaGetSymbolAddress((void**)&att16, g_att16);
    cudaGetSymbolAddress((void**)&x16, g_x16);
    cudaGetSymbolAddress((void**)&wq16, g_wq16);
    cudaGetSymbolAddress((void**)&wo16, g_wo16);
    cudaGetSymbolAddress((void**)&syncp, g_sync);

    static bool attr_done = false;
    if (!attr_done) {
        cudaFuncSetAttribute(mega, cudaFuncAttributeMaxDynamicSharedMemorySize, MEGA_SMEM);
        attr_done = true;
    }

    // 1) fp32 -> fp16 converts + sync reset
    {
        int n0 = (ML_ * KD_) / 4;
        int n1 = (NQKV_ * KD_) / 4;
        int n2 = (E_ * E_) / 4;
        int tot = n0 + n1 + n2;
        tohalf3<<<(tot + 255) / 256, 256>>>(
            (const float4*)x, (uint2*)x16, n0,
            (const float4*)W_qkv, (uint2*)wq16, n1,
            (const float4*)W_o, (uint2*)wo16, n2, syncp);
    }
    // 2) fused gemm1 -> attn -> gemm0 pipeline
    mega<<<MEGA_CTAS, 256, MEGA_SMEM>>>(
        x16, wq16, b_qkv, qkv16, pmask, att16, wo16, b_o, out);
}

// round 14
// speedup vs baseline: 1.0581x; 1.0345x over previous
#include <cuda_runtime.h>
#include <cuda_fp16.h>
#include <cstdint>
#include <math.h>

// Problem constants
#define B_    2
#define L_    2048
#define E_    1024
#define H_    16
#define HD_   64
#define KD_   1024
#define NQKV_ 3072
#define ML_   (B_*L_)   // 4096

// ---------------- GEMM tiling (fp16 single product) ----------------
#define BM 128
#define BN 128
#define BK 64
#define ROWB 144
#define B_OFF   (128 * ROWB)
#define STAGEB  (256 * ROWB)        // 36864
#define GEMM_SMEM (2 * STAGEB)      // 73728

// ---------------- attention tiling ----------------
#define AROWB 144
#define QROWS 128
#define KROWS 192
#define S_Q  0
#define S_K  (S_Q + QROWS*AROWB)
#define S_V  (S_K + KROWS*AROWB)
#define S_OK (S_V + KROWS*AROWB)
#define ATTN_SMEM (S_OK + KROWS*4)  // 74496

#define MEGA_SMEM (ATTN_SMEM > GEMM_SMEM ? ATTN_SMEM : GEMM_SMEM)
#define MEGA_CTAS 296

// Ticket layout: cvt (wq 192 | x 256 | wo 64) -> gemm1 -> attn -> gemm0
#define T_CVT  512
#define T_G1   768                  // 32 x 24
#define T_ATT  512                  // 16 qb x 2 b x 16 h
#define T_G0   256                  // 32 x 8
#define T_TOT  (T_CVT + T_G1 + T_ATT + T_G0)

// g_sync layout
#define SY_TICK 0
#define SY_G1   1                   // 768
#define SY_FA   769                 // 32
#define SY_FWQ  801                 // 192
#define SY_FX   993                 // 256
#define SY_FWO  1249                // 64
#define SY_DONE 1313
#define SY_N    1314

// ---------------- scratch ----------------
__device__ __half g_qkv16[(size_t)ML_ * NQKV_];
__device__ __half g_att16[(size_t)ML_ * E_];
__device__ __half g_x16[(size_t)ML_ * KD_];
__device__ __half g_wq16[(size_t)NQKV_ * KD_];
__device__ __half g_wo16[(size_t)E_ * E_];
__device__ unsigned g_sync[SY_N];   // zero-init; self-cleaned per launch

// ---------------- helpers ----------------
__device__ __forceinline__ uint32_t smem_u32(const void* p) {
    uint32_t a;
    asm("{ .reg .u64 t; cvta.to.shared.u64 t, %1; cvt.u32.u64 %0, t; }" : "=r"(a) : "l"(p));
    return a;
}
#define CP16(dst, src) \
    asm volatile("cp.async.cg.shared.global [%0], [%1], 16;" :: "r"(dst), "l"(src))
#define CP_COMMIT() asm volatile("cp.async.commit_group;" ::: "memory")
#define CP_WAIT(n)  asm volatile("cp.async.wait_group %0;" :: "n"(n) : "memory")

#define LDSM_X4(r0, r1, r2, r3, a) \
    asm volatile("ldmatrix.sync.aligned.m8n8.x4.shared.b16 {%0,%1,%2,%3}, [%4];" \
                 : "=r"(r0), "=r"(r1), "=r"(r2), "=r"(r3) : "r"(a))
#define LDSM_X4_T(r0, r1, r2, r3, a) \
    asm volatile("ldmatrix.sync.aligned.m8n8.x4.trans.shared.b16 {%0,%1,%2,%3}, [%4];" \
                 : "=r"(r0), "=r"(r1), "=r"(r2), "=r"(r3) : "r"(a))

__device__ __forceinline__ void mma_f16(float c[4], const uint32_t a[4],
                                        uint32_t b0, uint32_t b1) {
    asm volatile(
        "mma.sync.aligned.m16n8k16.row.col.f32.f16.f16.f32 "
        "{%0,%1,%2,%3}, {%4,%5,%6,%7}, {%8,%9}, {%0,%1,%2,%3};"
        : "+f"(c[0]), "+f"(c[1]), "+f"(c[2]), "+f"(c[3])
        : "r"(a[0]), "r"(a[1]), "r"(a[2]), "r"(a[3]), "r"(b0), "r"(b1));
}

__device__ __forceinline__ uint32_t pk_h2(float x, float y) {
    __half2 t = __floats2half2_rn(x, y);
    return *(uint32_t*)&t;
}

__device__ __forceinline__ void spin_flag(volatile unsigned* f) {
    while (*f == 0u) __nanosleep(64);
}

// ---------------------------------------------------------------------------
// One GEMM tile: C[bm:bm+128, bn:bn+128] = A*B^T + bias
// ---------------------------------------------------------------------------
template<bool F16OUT>
__device__ __forceinline__ void gemm_tile(
    char* smem, uint32_t sbase,
    const __half* __restrict__ A, const __half* __restrict__ Bm,
    const float* __restrict__ bias, float* __restrict__ Cf,
    uint32_t* __restrict__ Ch, int bm, int bn, int K, int N)
{
    const int tid  = threadIdx.x;
    const int lane = tid & 31;
    const int wid  = tid >> 5;
    const int warp_m = wid >> 1;
    const int warp_n = wid & 1;
    const int NT = K / BK;

    const int tr = tid >> 3;
    const int lc = tid & 7;
    const __half* Abase = A + (size_t)bm * K;
    const __half* Bbase = Bm + (size_t)bn * K;
    size_t offA[4];
    uint32_t dstA[4];
#pragma unroll
    for (int i = 0; i < 4; ++i) {
        int ra = i * 32 + tr;
        offA[i] = (size_t)ra * K + lc * 8;
        dstA[i] = (uint32_t)(ra * ROWB + lc * 16);
    }

    const uint32_t aOff = (uint32_t)((warp_m * 32 + (lane & 15)) * ROWB + (lane >> 4) * 16);
    const uint32_t bOff = (uint32_t)(B_OFF +
        (warp_n * 64 + ((lane >> 4) << 3) + (lane & 7)) * ROWB + ((lane >> 3) & 1) * 16);

    float acc[2][8][4];
#pragma unroll
    for (int mt = 0; mt < 2; ++mt)
#pragma unroll
        for (int nt = 0; nt < 8; ++nt)
#pragma unroll
            for (int j = 0; j < 4; ++j) acc[mt][nt][j] = 0.0f;

    {
        uint32_t sb = sbase;
#pragma unroll
        for (int i = 0; i < 4; ++i) {
            CP16(sb + dstA[i], Abase + offA[i]);
            CP16(sb + dstA[i] + B_OFF, Bbase + offA[i]);
        }
        CP_COMMIT();
    }

    for (int kt = 0; kt < NT; ++kt) {
        CP_WAIT(0);
        __syncthreads();
        if (kt + 1 < NT) {
            uint32_t sb = sbase + ((kt + 1) & 1) * STAGEB;
            int koff = (kt + 1) * BK;
#pragma unroll
            for (int i = 0; i < 4; ++i) {
                CP16(sb + dstA[i], Abase + offA[i] + koff);
                CP16(sb + dstA[i] + B_OFF, Bbase + offA[i] + koff);
            }
            CP_COMMIT();
        }

        const uint32_t st = sbase + (kt & 1) * STAGEB;
#pragma unroll
        for (int s = 0; s < 4; ++s) {
            uint32_t af[2][4], bf[8][2];
#pragma unroll
            for (int mt = 0; mt < 2; ++mt) {
                uint32_t a = st + aOff + mt * 16 * ROWB + s * 32;
                LDSM_X4(af[mt][0], af[mt][1], af[mt][2], af[mt][3], a);
            }
#pragma unroll
            for (int p = 0; p < 4; ++p) {
                uint32_t a = st + bOff + p * 16 * ROWB + s * 32;
                LDSM_X4(bf[2*p][0], bf[2*p][1], bf[2*p+1][0], bf[2*p+1][1], a);
            }
#pragma unroll
            for (int mt = 0; mt < 2; ++mt)
#pragma unroll
                for (int nt = 0; nt < 8; ++nt)
                    mma_f16(acc[mt][nt], af[mt], bf[nt][0], bf[nt][1]);
        }
        __syncthreads();
    }

    const int r0 = bm + warp_m * 32 + (lane >> 2);
    const int c0 = bn + warp_n * 64 + (lane & 3) * 2;
#pragma unroll
    for (int mt = 0; mt < 2; ++mt) {
#pragma unroll
        for (int nt = 0; nt < 8; ++nt) {
            int col = c0 + nt * 8;
            float bx = bias[col], by = bias[col + 1];
            float vx0 = acc[mt][nt][0] + bx, vy0 = acc[mt][nt][1] + by;
            float vx1 = acc[mt][nt][2] + bx, vy1 = acc[mt][nt][3] + by;
            int ra = r0 + mt * 16, rb = ra + 8;
            if (F16OUT) {
                Ch[(size_t)ra * (N >> 1) + (col >> 1)] = pk_h2(vx0, vy0);
                Ch[(size_t)rb * (N >> 1) + (col >> 1)] = pk_h2(vx1, vy1);
            } else {
                *(float2*)(Cf + (size_t)ra * N + col) = make_float2(vx0, vy0);
                *(float2*)(Cf + (size_t)rb * N + col) = make_float2(vx1, vy1);
            }
        }
    }
}

// ---------------------------------------------------------------------------
// One band-skipping attention tile (b, h, q0..q0+127), 256 threads.
// ---------------------------------------------------------------------------
__device__ __forceinline__ void attn_tile(
    char* smem, uint32_t sb,
    const __half* __restrict__ qkv, const int* __restrict__ pmask,
    uint32_t* __restrict__ Oh, int b, int h, int q0)
{
    const int tid = threadIdx.x, lane = tid & 31, w = tid >> 5;

    for (int i = tid; i < QROWS * 8; i += 256) {
        int r = i >> 3, c = i & 7;
        size_t g = (size_t)(b * L_ + q0 + r) * NQKV_ + h * 192 + c * 8;
        *(uint4*)(smem + S_Q + r * AROWB + c * 16) = *(const uint4*)(qkv + g);
    }
    for (int i = tid; i < KROWS * 8; i += 256) {
        int r = i >> 3, c = i & 7;
        int pos = q0 - 32 + r;
        uint4 kv = make_uint4(0, 0, 0, 0), vv = make_uint4(0, 0, 0, 0);
        if (pos >= 0 && pos < L_) {
            size_t g = (size_t)(b * L_ + pos) * NQKV_ + h * 192 + c * 8;
            kv = *(const uint4*)(qkv + g + 64);
            vv = *(const uint4*)(qkv + g + 128);
        }
        *(uint4*)(smem + S_K + r * AROWB + c * 16) = kv;
        *(uint4*)(smem + S_V + r * AROWB + c * 16) = vv;
    }
    if (tid < KROWS) {
        int pos = q0 - 32 + tid;
        int ok = (pos >= 0 && pos < L_) ? (pmask[b * L_ + pos] != 0) : 0;
        ((int*)(smem + S_OK))[tid] = ok;
    }
    __syncthreads();
    const int* okk = (const int*)(smem + S_OK);

    float S[10][4];
#pragma unroll
    for (int i = 0; i < 10; ++i)
#pragma unroll
        for (int j = 0; j < 4; ++j) S[i][j] = 0.0f;

    uint32_t qf[4][4];
    {
        uint32_t aoff = (uint32_t)((w * 16 + (lane & 15)) * AROWB + (lane >> 4) * 16);
#pragma unroll
        for (int ks = 0; ks < 4; ++ks)
            LDSM_X4(qf[ks][0], qf[ks][1], qf[ks][2], qf[ks][3], sb + S_Q + aoff + ks * 32);
    }
    {
        uint32_t boff = (uint32_t)(((((lane >> 4) << 3) + (lane & 7)) * AROWB) + ((lane >> 3) & 1) * 16);
#pragma unroll
        for (int kbl = 0; kbl < 5; ++kbl) {
            uint32_t base = boff + (w + kbl) * 16 * AROWB;
#pragma unroll
            for (int ks = 0; ks < 4; ++ks) {
                uint32_t b0, b1, b2, b3;
                LDSM_X4(b0, b1, b2, b3, sb + S_K + base + ks * 32);
                mma_f16(S[2 * kbl],     qf[ks], b0, b1);
                mma_f16(S[2 * kbl + 1], qf[ks], b2, b3);
            }
        }
    }

    const int qlo = w * 16 + (lane >> 2);
    const float scale = 0.125f;
    const float NEGS = -12500.0f;
    float mlo = -3.0e38f, mhi = -3.0e38f;
#pragma unroll
    for (int nbl = 0; nbl < 10; ++nbl) {
        int kbl = nbl >> 1, grp = nbl & 1;
#pragma unroll
        for (int p = 0; p < 2; ++p) {
            int j = (w + kbl) * 16 + grp * 8 + (lane & 3) * 2 + p;
            float s0 = S[nbl][p];
            int d0 = j - qlo;
            s0 = (d0 >= 0 && d0 <= 64) ? (okk[j] ? s0 * scale : NEGS) : -3.0e38f;
            S[nbl][p] = s0;
            mlo = fmaxf(mlo, s0);
            float s1 = S[nbl][2 + p];
            int d1 = j - (qlo + 8);
            s1 = (d1 >= 0 && d1 <= 64) ? (okk[j] ? s1 * scale : NEGS) : -3.0e38f;
            S[nbl][2 + p] = s1;
            mhi = fmaxf(mhi, s1);
        }
    }
#pragma unroll
    for (int o = 1; o <= 2; o <<= 1) {
        mlo = fmaxf(mlo, __shfl_xor_sync(0xffffffffu, mlo, o));
        mhi = fmaxf(mhi, __shfl_xor_sync(0xffffffffu, mhi, o));
    }
    float slo = 0.f, shi = 0.f;
#pragma unroll
    for (int nbl = 0; nbl < 10; ++nbl) {
#pragma unroll
        for (int p = 0; p < 2; ++p) {
            float e0 = __expf(S[nbl][p] - mlo);     S[nbl][p] = e0;     slo += e0;
            float e1 = __expf(S[nbl][2 + p] - mhi); S[nbl][2 + p] = e1; shi += e1;
        }
    }
#pragma unroll
    for (int o = 1; o <= 2; o <<= 1) {
        slo += __shfl_xor_sync(0xffffffffu, slo, o);
        shi += __shfl_xor_sync(0xffffffffu, shi, o);
    }
    const float invlo = 1.0f / slo;
    const float invhi = 1.0f / shi;

    uint32_t pf[5][4];
#pragma unroll
    for (int kbl = 0; kbl < 5; ++kbl) {
        pf[kbl][0] = pk_h2(S[2 * kbl][0] * invlo,     S[2 * kbl][1] * invlo);
        pf[kbl][1] = pk_h2(S[2 * kbl][2] * invhi,     S[2 * kbl][3] * invhi);
        pf[kbl][2] = pk_h2(S[2 * kbl + 1][0] * invlo, S[2 * kbl + 1][1] * invlo);
        pf[kbl][3] = pk_h2(S[2 * kbl + 1][2] * invhi, S[2 * kbl + 1][3] * invhi);
    }

    float O[8][4];
#pragma unroll
    for (int i = 0; i < 8; ++i)
#pragma unroll
        for (int j = 0; j < 4; ++j) O[i][j] = 0.0f;

    {
        uint32_t voff = (uint32_t)((lane & 15) * AROWB + (lane >> 4) * 16);
#pragma unroll
        for (int kbl = 0; kbl < 5; ++kbl) {
            uint32_t base = voff + (w + kbl) * 16 * AROWB;
#pragma unroll
            for (int db = 0; db < 4; ++db) {
                uint32_t v0, v1, v2, v3;
                LDSM_X4_T(v0, v1, v2, v3, sb + S_V + base + db * 32);
                mma_f16(O[2 * db],     pf[kbl], v0, v1);
                mma_f16(O[2 * db + 1], pf[kbl], v2, v3);
            }
        }
    }

    const size_t rowlo = (size_t)(b * L_ + q0 + qlo);
    const size_t rowhi = rowlo + 8;
#pragma unroll
    for (int nb = 0; nb < 8; ++nb) {
        int col = h * 64 + nb * 8 + (lane & 3) * 2;
        Oh[rowlo * (E_ / 2) + (col >> 1)] = pk_h2(O[nb][0], O[nb][1]);
        Oh[rowhi * (E_ / 2) + (col >> 1)] = pk_h2(O[nb][2], O[nb][3]);
    }
}

// ---------------------------------------------------------------------------
// Convert one 16-row x 1024-col fp32 chunk to fp16 (MLP-batched).
// 4096 float4 in, 2048 uint4 out; per thread: 16 loads / 8 stores.
// ---------------------------------------------------------------------------
__device__ __forceinline__ void convert_chunk(
    const float4* __restrict__ src, uint4* __restrict__ dst, int tid)
{
#pragma unroll
    for (int p = 0; p < 2; ++p) {
        float4 a[4], b[4];
#pragma unroll
        for (int j = 0; j < 4; ++j) {
            int idx = (p * 4 + j) * 256 + tid;      // uint4 index, 0..2047
            a[j] = src[2 * idx];
            b[j] = src[2 * idx + 1];
        }
#pragma unroll
        for (int j = 0; j < 4; ++j) {
            int idx = (p * 4 + j) * 256 + tid;
            dst[idx] = make_uint4(pk_h2(a[j].x, a[j].y), pk_h2(a[j].z, a[j].w),
                                  pk_h2(b[j].x, b[j].y), pk_h2(b[j].z, b[j].w));
        }
    }
}

// ---------------------------------------------------------------------------
// Fully fused pipeline: cvt -> gemm1 -> attn -> gemm0, flag-gated.
// Self-cleans g_sync at the end for graph replay.
// ---------------------------------------------------------------------------
__global__ __launch_bounds__(256, 2) void mega(
    const float* __restrict__ x, const float* __restrict__ W_qkv,
    const float* __restrict__ W_o,
    const float* __restrict__ b_qkv, const float* __restrict__ b_o,
    const int* __restrict__ pmask, float* __restrict__ out)
{
    extern __shared__ char smem[];
    __shared__ unsigned s_t;
    const uint32_t sbase = smem_u32(smem);
    const int tid = threadIdx.x;
    unsigned* tick = &g_sync[SY_TICK];
    unsigned* g1   = &g_sync[SY_G1];
    unsigned* fa   = &g_sync[SY_FA];
    unsigned* fwq  = &g_sync[SY_FWQ];
    unsigned* fx   = &g_sync[SY_FX];
    unsigned* fwo  = &g_sync[SY_FWO];

    for (;;) {
        __syncthreads();
        if (tid == 0) s_t = atomicAdd(tick, 1u);
        __syncthreads();
        const unsigned t = s_t;
        if (t >= (unsigned)T_TOT) break;

        if (t < (unsigned)T_CVT) {
            // fine-grained convert: 16-row chunk of one source tensor
            const float4* src;
            uint4* dst;
            unsigned* flag;
            if (t < 192u) {           // W_qkv chunk
                src  = (const float4*)W_qkv + (size_t)t * 4096;
                dst  = (uint4*)g_wq16 + (size_t)t * 2048;
                flag = &fwq[t];
            } else if (t < 448u) {    // x chunk
                unsigned c = t - 192u;
                src  = (const float4*)x + (size_t)c * 4096;
                dst  = (uint4*)g_x16 + (size_t)c * 2048;
                flag = &fx[c];
            } else {                  // W_o chunk
                unsigned c = t - 448u;
                src  = (const float4*)W_o + (size_t)c * 4096;
                dst  = (uint4*)g_wo16 + (size_t)c * 2048;
                flag = &fwo[c];
            }
            convert_chunk(src, dst, tid);
            __threadfence();
            __syncthreads();
            if (tid == 0) atomicExch(flag, 1u);
        } else if (t < (unsigned)(T_CVT + T_G1)) {
            // QKV projection tile; batches interleaved so early rows finish first
            unsigned u = t - T_CVT;
            int i = (int)u / 24, bn_i = (int)u % 24;
            int bm_i = ((i & 1) << 4) + (i >> 1);
            // parallel spin: threads 0-7 on x chunks, 8-15 on wq chunks
            if (tid < 8)        spin_flag(&fx[bm_i * 8 + tid]);
            else if (tid < 16)  spin_flag(&fwq[bn_i * 8 + (tid - 8)]);
            __syncthreads();
            gemm_tile<true>(smem, sbase, g_x16, g_wq16, b_qkv, nullptr,
                            (uint32_t*)g_qkv16, bm_i * 128, bn_i * 128, KD_, NQKV_);
            __threadfence();
            __syncthreads();
            if (tid == 0) atomicExch(&g1[bm_i * 24 + bn_i], 1u);
        } else if (t < (unsigned)(T_CVT + T_G1 + T_ATT)) {
            // attention tile
            unsigned a = t - (T_CVT + T_G1);
            int qb = (int)(a >> 5), b = (int)((a >> 4) & 1), h = (int)(a & 15);
            if (tid == 0) {
                int ct0 = (3 * h) >> 1;
                for (int rb = qb - 1; rb <= qb + 1; ++rb) {
                    if (rb < 0 || rb > 15) continue;
                    int base = (b * 16 + rb) * 24 + ct0;
                    spin_flag(&g1[base]);
                    spin_flag(&g1[base + 1]);
                }
            }
            __syncthreads();
            attn_tile(smem, sbase, g_qkv16, pmask, (uint32_t*)g_att16, b, h, qb * 128);
            __threadfence();
            __syncthreads();
            if (tid == 0) atomicAdd(&fa[b * 16 + qb], 1u);
        } else {
            // output projection tile
            unsigned g = t - (T_CVT + T_G1 + T_ATT);
            int j = (int)(g >> 3), bn_i = (int)(g & 7);
            int bm_i = ((j & 1) << 4) + (j >> 1);
            if (tid < 8) spin_flag(&fwo[bn_i * 8 + tid]);
            else if (tid == 8) {
                while (((volatile unsigned*)fa)[bm_i] < 16u) __nanosleep(64);
            }
            __syncthreads();
            gemm_tile<false>(smem, sbase, g_att16, g_wo16, b_o, out,
                             nullptr, bm_i * 128, bn_i * 128, KD_, E_);
        }
    }

    // ---- self-clean: last CTA resets g_sync for next launch/replay ----
    __threadfence();
    __syncthreads();
    if (tid == 0)
        s_t = (atomicAdd(&g_sync[SY_DONE], 1u) == (unsigned)(gridDim.x - 1)) ? 1u : 0u;
    __syncthreads();
    if (s_t) {
        for (int i = tid; i < SY_N; i += 256) g_sync[i] = 0u;
    }
}

// ---------------------------------------------------------------------------
// kernel_launch
// ---------------------------------------------------------------------------
extern "C" void kernel_launch(void* const* d_in, const int* in_sizes, int n_in,
                              void* d_out, int out_size)
{
    const float* x      = (const float*)d_in[0];
    const int*   pmask  = (const int*)d_in[1];
    const float* W_qkv  = (const float*)d_in[2];
    const float* b_qkv  = (const float*)d_in[3];
    const float* W_o    = (const float*)d_in[4];
    const float* b_o    = (const float*)d_in[5];
    float* out = (float*)d_out;

    static bool attr_done = false;
    if (!attr_done) {
        cudaFuncSetAttribute(mega, cudaFuncAttributeMaxDynamicSharedMemorySize, MEGA_SMEM);
        attr_done = true;
    }

    mega<<<MEGA_CTAS, 256, MEGA_SMEM>>>(x, W_qkv, W_o, b_qkv, b_o, pmask, out);
}